// round 5
// baseline (speedup 1.0000x reference)
#include <cuda_runtime.h>

// NeuralODE: encoder -> 99 RK4 steps -> decoder at every timestep.
// E=1 element/thread (64K threads). Weight traffic split between the
// constant port (LDC/LDCU, warp-uniform addresses) and shared memory,
// because the L1 return path replicates broadcast LDS across lanes
// (measured ~6 cyc per LDS.128). Layer-1 uses k-outer accumulation so
// raw [16][50] layouts need no transpose. h kept as 25 packed f32x2.

#define HID 50
#define LAT 16
#define ROWP 52   // padded row stride (floats) for [16][50] matrices; 208B, 16B-aligned

typedef unsigned long long u64;

__constant__ float c_wo1[16 * ROWP];    // ODE layer1 weights, rows k=0..15 (k<8 read here)
__constant__ float c_wd1[16 * ROWP];    // decoder layer1 weights
__constant__ float c_wo2hi[18 * LAT];   // ODE layer2 rows (hidden units 32..49)

__device__ __forceinline__ u64 pk2(float a, float b) {
    u64 v; asm("mov.b64 %0, {%1,%2};" : "=l"(v) : "f"(a), "f"(b)); return v;
}
__device__ __forceinline__ float2 up2(u64 v) {
    float2 r; asm("mov.b64 {%0,%1}, %2;" : "=f"(r.x), "=f"(r.y) : "l"(v)); return r;
}
__device__ __forceinline__ u64 ffma2(u64 a, u64 b, u64 c) {
    u64 d; asm("fma.rn.f32x2 %0, %1, %2, %3;" : "=l"(d) : "l"(a), "l"(b), "l"(c)); return d;
}
__device__ __forceinline__ u64 fadd2(u64 a, u64 b) {
    u64 d; asm("add.rn.f32x2 %0, %1, %2;" : "=l"(d) : "l"(a), "l"(b)); return d;
}

// tanh(x) = 1 - 2/(1+e^{2x});  ~1e-6 rel err, saturates correctly.
__device__ __forceinline__ float tanh_fast(float x) {
    float e = __expf(2.0f * x);
    return 1.0f - __fdividef(2.0f, e + 1.0f);
}

struct __align__(16) SW {
    float wo1[16 * ROWP];   // raw Wo1 rows (k=8..15 read here)
    float wd1[16 * ROWP];   // raw Wd1 rows (k=8..15 read here)
    float wo2lo[32 * LAT];  // Wo2 rows, hidden units 0..31
    float we2[HID * LAT];   // encoder layer2, natural rows
    float wd2p[ROWP];       // Wd2, padded (read as u64 pairs)
    float bo1p[ROWP];       // bo1 padded (u64 pairs)
    float bd1p[ROWP];       // bd1 padded
    float bo2[LAT];
    float be2[LAT];
    float be1[HID];
    float we1a[HID];
    float we1b[HID];
    float dt[128];
    float bd2;
};

// ODE f: kk = tanh(zt @ Wo1 + bo1) @ Wo2 + bo2.  zt, kk packed (8 u64).
__device__ __forceinline__ void ode_f(const u64 zt[8], u64 kk[8], const SW& s) {
    u64 h2[25];
    const u64* bp = (const u64*)s.bo1p;
#pragma unroll
    for (int j = 0; j < 25; j++) h2[j] = bp[j];

    // ---- layer1, k-outer.  k=0..7 from constant, k=8..15 from smem ----
#pragma unroll
    for (int k = 0; k < 8; k++) {
        float2 zp = up2(zt[k >> 1]);
        float zk = (k & 1) ? zp.y : zp.x;
        u64 zd = pk2(zk, zk);
        const ulonglong2* r2 = (const ulonglong2*)(c_wo1 + k * ROWP);
#pragma unroll
        for (int j = 0; j < 12; j++) {
            ulonglong2 w = r2[j];
            h2[2 * j]     = ffma2(zd, w.x, h2[2 * j]);
            h2[2 * j + 1] = ffma2(zd, w.y, h2[2 * j + 1]);
        }
        h2[24] = ffma2(zd, ((const u64*)(c_wo1 + k * ROWP))[24], h2[24]);
    }
#pragma unroll
    for (int k = 8; k < 16; k++) {
        float2 zp = up2(zt[k >> 1]);
        float zk = (k & 1) ? zp.y : zp.x;
        u64 zd = pk2(zk, zk);
        const ulonglong2* r2 = (const ulonglong2*)(s.wo1 + k * ROWP);
#pragma unroll
        for (int j = 0; j < 12; j++) {
            ulonglong2 w = r2[j];
            h2[2 * j]     = ffma2(zd, w.x, h2[2 * j]);
            h2[2 * j + 1] = ffma2(zd, w.y, h2[2 * j + 1]);
        }
        h2[24] = ffma2(zd, ((const u64*)(s.wo1 + k * ROWP))[24], h2[24]);
    }

    // ---- layer2: kk += tanh(h_i) * Wo2[i][:].  units 0..31 smem, 32..49 const ----
    const u64* bo2p = (const u64*)s.bo2;
#pragma unroll
    for (int j = 0; j < 8; j++) kk[j] = bo2p[j];

#pragma unroll
    for (int j2 = 0; j2 < 16; j2++) {
        float2 hp = up2(h2[j2]);
        float hA = tanh_fast(hp.x);
        float hB = tanh_fast(hp.y);
        u64 da = pk2(hA, hA), db = pk2(hB, hB);
        const ulonglong2* ra = (const ulonglong2*)(s.wo2lo + (2 * j2) * LAT);
#pragma unroll
        for (int m = 0; m < 4; m++) {
            ulonglong2 wa = ra[m];
            kk[2 * m]     = ffma2(da, wa.x, kk[2 * m]);
            kk[2 * m + 1] = ffma2(da, wa.y, kk[2 * m + 1]);
        }
#pragma unroll
        for (int m = 0; m < 4; m++) {
            ulonglong2 wb = ra[4 + m];
            kk[2 * m]     = ffma2(db, wb.x, kk[2 * m]);
            kk[2 * m + 1] = ffma2(db, wb.y, kk[2 * m + 1]);
        }
    }
#pragma unroll
    for (int j2 = 16; j2 < 25; j2++) {
        float2 hp = up2(h2[j2]);
        float hA = tanh_fast(hp.x);
        float hB = tanh_fast(hp.y);
        u64 da = pk2(hA, hA), db = pk2(hB, hB);
        const ulonglong2* ra = (const ulonglong2*)(c_wo2hi + (2 * j2 - 32) * LAT);
#pragma unroll
        for (int m = 0; m < 4; m++) {
            ulonglong2 wa = ra[m];
            kk[2 * m]     = ffma2(da, wa.x, kk[2 * m]);
            kk[2 * m + 1] = ffma2(da, wa.y, kk[2 * m + 1]);
        }
#pragma unroll
        for (int m = 0; m < 4; m++) {
            ulonglong2 wb = ra[4 + m];
            kk[2 * m]     = ffma2(db, wb.x, kk[2 * m]);
            kk[2 * m + 1] = ffma2(db, wb.y, kk[2 * m + 1]);
        }
    }
}

// Decoder: y = relu(z @ Wd1 + bd1) @ Wd2 + bd2.
__device__ __forceinline__ float decode(const u64 z[8], const SW& s) {
    u64 h2[25];
    const u64* bp = (const u64*)s.bd1p;
#pragma unroll
    for (int j = 0; j < 25; j++) h2[j] = bp[j];

#pragma unroll
    for (int k = 0; k < 8; k++) {
        float2 zp = up2(z[k >> 1]);
        float zk = (k & 1) ? zp.y : zp.x;
        u64 zd = pk2(zk, zk);
        const ulonglong2* r2 = (const ulonglong2*)(c_wd1 + k * ROWP);
#pragma unroll
        for (int j = 0; j < 12; j++) {
            ulonglong2 w = r2[j];
            h2[2 * j]     = ffma2(zd, w.x, h2[2 * j]);
            h2[2 * j + 1] = ffma2(zd, w.y, h2[2 * j + 1]);
        }
        h2[24] = ffma2(zd, ((const u64*)(c_wd1 + k * ROWP))[24], h2[24]);
    }
#pragma unroll
    for (int k = 8; k < 16; k++) {
        float2 zp = up2(z[k >> 1]);
        float zk = (k & 1) ? zp.y : zp.x;
        u64 zd = pk2(zk, zk);
        const ulonglong2* r2 = (const ulonglong2*)(s.wd1 + k * ROWP);
#pragma unroll
        for (int j = 0; j < 12; j++) {
            ulonglong2 w = r2[j];
            h2[2 * j]     = ffma2(zd, w.x, h2[2 * j]);
            h2[2 * j + 1] = ffma2(zd, w.y, h2[2 * j + 1]);
        }
        h2[24] = ffma2(zd, ((const u64*)(s.wd1 + k * ROWP))[24], h2[24]);
    }

    // y accumulation with ReLU, packed pairs
    u64 y2 = 0;
    const u64* wd2 = (const u64*)s.wd2p;
#pragma unroll
    for (int j = 0; j < 25; j++) {
        float2 hp = up2(h2[j]);
        hp.x = fmaxf(hp.x, 0.0f);
        hp.y = fmaxf(hp.y, 0.0f);
        y2 = ffma2(pk2(hp.x, hp.y), wd2[j], y2);
    }
    float2 yy = up2(y2);
    return yy.x + yy.y + s.bd2;
}

__global__ void __launch_bounds__(64)
node_kernel(const float* __restrict__ x0, const float* __restrict__ t,
            const float* __restrict__ We1, const float* __restrict__ be1,
            const float* __restrict__ We2, const float* __restrict__ be2,
            const float* __restrict__ Wo1, const float* __restrict__ bo1,
            const float* __restrict__ Wo2, const float* __restrict__ bo2,
            const float* __restrict__ Wd1, const float* __restrict__ bd1,
            const float* __restrict__ Wd2, const float* __restrict__ bd2,
            float* __restrict__ out, int Bn, int Tn) {
    __shared__ SW s;
    int tid = threadIdx.x;

    // stage weights (raw layouts, padded rows)
    for (int idx = tid; idx < 16 * ROWP; idx += blockDim.x) {
        int k = idx / ROWP, i = idx % ROWP;
        float vo = (i < HID) ? Wo1[k * HID + i] : 0.0f;
        float vd = (i < HID) ? Wd1[k * HID + i] : 0.0f;
        s.wo1[idx] = vo;
        s.wd1[idx] = vd;
    }
    for (int idx = tid; idx < 32 * LAT; idx += blockDim.x) s.wo2lo[idx] = Wo2[idx];
    for (int idx = tid; idx < HID * LAT; idx += blockDim.x) s.we2[idx] = We2[idx];
    for (int idx = tid; idx < ROWP; idx += blockDim.x) {
        s.wd2p[idx] = (idx < HID) ? Wd2[idx] : 0.0f;
        s.bo1p[idx] = (idx < HID) ? bo1[idx] : 0.0f;
        s.bd1p[idx] = (idx < HID) ? bd1[idx] : 0.0f;
    }
    for (int idx = tid; idx < HID; idx += blockDim.x) {
        s.be1[idx]  = be1[idx];
        s.we1a[idx] = We1[idx];
        s.we1b[idx] = We1[HID + idx];
    }
    for (int idx = tid; idx < LAT; idx += blockDim.x) {
        s.bo2[idx] = bo2[idx];
        s.be2[idx] = be2[idx];
    }
    for (int idx = tid; idx < Tn - 1 && idx < 128; idx += blockDim.x)
        s.dt[idx] = t[idx + 1] - t[idx];
    if (tid == 0) s.bd2 = bd2[0];
    __syncthreads();

    int b = blockIdx.x * blockDim.x + tid;
    if (b >= Bn) return;

    // ---------- Encoder: z0 = relu(x0@We1 + be1) @ We2 + be2 ----------
    float2 x = ((const float2*)x0)[b];
    u64 z[8];
    {
        const u64* be2p = (const u64*)s.be2;
#pragma unroll
        for (int j = 0; j < 8; j++) z[j] = be2p[j];
#pragma unroll 5
        for (int i = 0; i < HID; i++) {
            float h = fmaf(x.y, s.we1b[i], fmaf(x.x, s.we1a[i], s.be1[i]));
            h = fmaxf(h, 0.0f);
            u64 hd = pk2(h, h);
            const ulonglong2* w = (const ulonglong2*)(s.we2 + i * LAT);
#pragma unroll
            for (int j = 0; j < 4; j++) {
                ulonglong2 ww = w[j];
                z[2 * j]     = ffma2(hd, ww.x, z[2 * j]);
                z[2 * j + 1] = ffma2(hd, ww.y, z[2 * j + 1]);
            }
        }
    }

    out[b] = decode(z, s);  // t = 0

    // ---------- RK4 time stepping (rolled stage loop, 1 copy of f) ----------
    for (int st = 0; st < Tn - 1; ++st) {
        float dtv = s.dt[st];
        float h6 = dtv * (1.0f / 6.0f);
        float h3 = dtv * (1.0f / 3.0f);
        float hf = dtv * 0.5f;

        u64 zn[8], zt[8], kk[8];
#pragma unroll
        for (int j = 0; j < 8; j++) { zn[j] = z[j]; zt[j] = z[j]; }

        for (int stage = 0; stage < 4; ++stage) {
            ode_f(zt, kk, s);
            float ws = (stage == 1 || stage == 2) ? h3 : h6;
            u64 wsp = pk2(ws, ws);
#pragma unroll
            for (int j = 0; j < 8; j++) zn[j] = ffma2(wsp, kk[j], zn[j]);
            if (stage < 3) {
                float as = (stage == 2) ? dtv : hf;
                u64 asp = pk2(as, as);
#pragma unroll
                for (int j = 0; j < 8; j++) zt[j] = ffma2(asp, kk[j], z[j]);
            }
        }
#pragma unroll
        for (int j = 0; j < 8; j++) z[j] = zn[j];

        out[(size_t)(st + 1) * Bn + b] = decode(z, s);
    }
}

extern "C" void kernel_launch(void* const* d_in, const int* in_sizes, int n_in,
                              void* d_out, int out_size) {
    const float* x0  = (const float*)d_in[0];
    const float* t   = (const float*)d_in[1];
    const float* We1 = (const float*)d_in[2];
    const float* be1 = (const float*)d_in[3];
    const float* We2 = (const float*)d_in[4];
    const float* be2 = (const float*)d_in[5];
    const float* Wo1 = (const float*)d_in[6];
    const float* bo1 = (const float*)d_in[7];
    const float* Wo2 = (const float*)d_in[8];
    const float* bo2 = (const float*)d_in[9];
    const float* Wd1 = (const float*)d_in[10];
    const float* bd1 = (const float*)d_in[11];
    const float* Wd2 = (const float*)d_in[12];
    const float* bd2 = (const float*)d_in[13];

    int Bn = in_sizes[0] / 2;   // x0 is (B, 2)
    int Tn = in_sizes[1];       // t is (T,)

    // Stage weights into constant memory (D2D async memcpys; graph-capturable).
    // Rows padded to ROWP floats for 16B-aligned vector loads.
    for (int k = 0; k < 16; k++) {
        cudaMemcpyToSymbolAsync(c_wo1, Wo1 + k * HID, HID * sizeof(float),
                                k * ROWP * sizeof(float), cudaMemcpyDeviceToDevice, 0);
        cudaMemcpyToSymbolAsync(c_wd1, Wd1 + k * HID, HID * sizeof(float),
                                k * ROWP * sizeof(float), cudaMemcpyDeviceToDevice, 0);
    }
    cudaMemcpyToSymbolAsync(c_wo2hi, Wo2 + 32 * LAT, 18 * LAT * sizeof(float),
                            0, cudaMemcpyDeviceToDevice, 0);

    int threads = 64;
    int blocks = (Bn + threads - 1) / threads;
    node_kernel<<<blocks, threads>>>(x0, t, We1, be1, We2, be2, Wo1, bo1,
                                     Wo2, bo2, Wd1, bd1, Wd2, bd2,
                                     (float*)d_out, Bn, Tn);
}

// round 6
// speedup vs baseline: 7.0830x; 7.0830x over previous
#include <cuda_runtime.h>

// NeuralODE: encoder -> 99 RK4 steps -> decoder at every timestep.
// Lane-pair scheme: lanes (l, l^16) jointly own TWO elements (eA, eB).
// Lane l computes hidden units [0,25) for both, lane l^16 units [25,50);
// partial k combined via shfl_xor(16). This keeps 2048 warps (latency
// hiding, R2 level) at halved per-element LDS traffic (R3 level).

#define HID 50
#define LAT 16

typedef unsigned long long u64;

__device__ __forceinline__ u64 pk2(float a, float b) {
    u64 v; asm("mov.b64 %0, {%1,%2};" : "=l"(v) : "f"(a), "f"(b)); return v;
}
__device__ __forceinline__ float2 up2(u64 v) {
    float2 r; asm("mov.b64 {%0,%1}, %2;" : "=f"(r.x), "=f"(r.y) : "l"(v)); return r;
}
__device__ __forceinline__ u64 ffma2(u64 a, u64 b, u64 c) {
    u64 d; asm("fma.rn.f32x2 %0, %1, %2, %3;" : "=l"(d) : "l"(a), "l"(b), "l"(c)); return d;
}
__device__ __forceinline__ u64 fmul2(u64 a, u64 b) {
    u64 d; asm("mul.rn.f32x2 %0, %1, %2;" : "=l"(d) : "l"(a), "l"(b)); return d;
}
__device__ __forceinline__ u64 fadd2(u64 a, u64 b) {
    u64 d; asm("add.rn.f32x2 %0, %1, %2;" : "=l"(d) : "l"(a), "l"(b)); return d;
}

// tanh(x) = 1 - 2/(1+e^{2x});  ~1e-6 rel err, saturates correctly.
__device__ __forceinline__ float tanh_fast(float x) {
    float e = __expf(2.0f * x);
    return 1.0f - __fdividef(2.0f, e + 1.0f);
}

struct __align__(16) SW {
    float wo1t[HID * LAT];  // wo1t[i*16+k] = Wo1[k][i]
    float wo2 [HID * LAT];  // Wo2[i][j], row-major
    float we2 [HID * LAT];  // We2[i][k], row-major
    float wd1t[HID * LAT];  // wd1t[i*16+k] = Wd1[k][i]
    float bo2[LAT];
    float be2[LAT];
    float bo1[HID];
    float be1[HID];
    float bd1[HID];
    float we1a[HID];        // We1[0][i]
    float we1b[HID];        // We1[1][i]
    float wd2[HID];
    float dt[128];
    float bd2;
};

// dot of 16-dim packed z with a weight row already in registers
__device__ __forceinline__ float rdot(const u64 zp[8], ulonglong2 w0, ulonglong2 w1,
                                      ulonglong2 w2, ulonglong2 w3) {
    u64 a0 = fmul2(zp[0], w0.x);
    u64 a1 = fmul2(zp[1], w0.y);
    a0 = ffma2(zp[2], w1.x, a0);
    a1 = ffma2(zp[3], w1.y, a1);
    a0 = ffma2(zp[4], w2.x, a0);
    a1 = ffma2(zp[5], w2.y, a1);
    a0 = ffma2(zp[6], w3.x, a0);
    a1 = ffma2(zp[7], w3.y, a1);
    float2 p = up2(fadd2(a0, a1));
    return p.x + p.y;
}

// Partial f over this lane's 25 hidden units for BOTH elements,
// then combine partial k across the lane pair (shfl_xor 16).
__device__ __forceinline__ void ode_f2(const u64 zA[8], const u64 zB[8],
                                       u64 kA[8], u64 kB[8], const SW& s,
                                       int i0, int half) {
    const u64* bo2p = (const u64*)s.bo2;
#pragma unroll
    for (int j = 0; j < 8; j++) {
        kA[j] = half ? 0ull : bo2p[j];
        kB[j] = kA[j];
    }
#pragma unroll 5
    for (int ii = 0; ii < HID / 2; ii++) {
        int i = i0 + ii;
        const ulonglong2* w = (const ulonglong2*)(s.wo1t + i * LAT);
        ulonglong2 w0 = w[0], w1 = w[1], w2 = w[2], w3 = w[3];
        float b1 = s.bo1[i];
        float hA = tanh_fast(rdot(zA, w0, w1, w2, w3) + b1);
        float hB = tanh_fast(rdot(zB, w0, w1, w2, w3) + b1);
        u64 hA2 = pk2(hA, hA), hB2 = pk2(hB, hB);
        const ulonglong2* v = (const ulonglong2*)(s.wo2 + i * LAT);
#pragma unroll
        for (int j = 0; j < 4; j++) {
            ulonglong2 vv = v[j];
            kA[2 * j]     = ffma2(hA2, vv.x, kA[2 * j]);
            kA[2 * j + 1] = ffma2(hA2, vv.y, kA[2 * j + 1]);
            kB[2 * j]     = ffma2(hB2, vv.x, kB[2 * j]);
            kB[2 * j + 1] = ffma2(hB2, vv.y, kB[2 * j + 1]);
        }
    }
#pragma unroll
    for (int j = 0; j < 8; j++) {
        kA[j] = fadd2(kA[j], __shfl_xor_sync(0xffffffffu, kA[j], 16));
        kB[j] = fadd2(kB[j], __shfl_xor_sync(0xffffffffu, kB[j], 16));
    }
}

// Partial decode over this lane's 25 hidden units, combined across pair.
__device__ __forceinline__ float2 decode2(const u64 zA[8], const u64 zB[8],
                                          const SW& s, int i0, int half) {
    float yA = half ? 0.0f : s.bd2;
    float yB = yA;
#pragma unroll 5
    for (int ii = 0; ii < HID / 2; ii++) {
        int i = i0 + ii;
        const ulonglong2* w = (const ulonglong2*)(s.wd1t + i * LAT);
        ulonglong2 w0 = w[0], w1 = w[1], w2 = w[2], w3 = w[3];
        float b1 = s.bd1[i], wd = s.wd2[i];
        float hA = fmaxf(rdot(zA, w0, w1, w2, w3) + b1, 0.0f);
        float hB = fmaxf(rdot(zB, w0, w1, w2, w3) + b1, 0.0f);
        yA = fmaf(hA, wd, yA);
        yB = fmaf(hB, wd, yB);
    }
    yA += __shfl_xor_sync(0xffffffffu, yA, 16);
    yB += __shfl_xor_sync(0xffffffffu, yB, 16);
    return make_float2(yA, yB);
}

__global__ void __launch_bounds__(64)
node_kernel(const float* __restrict__ x0, const float* __restrict__ t,
            const float* __restrict__ We1, const float* __restrict__ be1,
            const float* __restrict__ We2, const float* __restrict__ be2,
            const float* __restrict__ Wo1, const float* __restrict__ bo1,
            const float* __restrict__ Wo2, const float* __restrict__ bo2,
            const float* __restrict__ Wd1, const float* __restrict__ bd1,
            const float* __restrict__ Wd2, const float* __restrict__ bd2,
            float* __restrict__ out, int Bn, int Tn) {
    __shared__ SW s;
    int tid = threadIdx.x;

    for (int idx = tid; idx < HID * LAT; idx += blockDim.x) {
        int i = idx >> 4, k = idx & 15;
        s.wo1t[idx] = Wo1[k * HID + i];
        s.wd1t[idx] = Wd1[k * HID + i];
        s.wo2[idx]  = Wo2[idx];
        s.we2[idx]  = We2[idx];
    }
    for (int idx = tid; idx < HID; idx += blockDim.x) {
        s.bo1[idx]  = bo1[idx];
        s.be1[idx]  = be1[idx];
        s.bd1[idx]  = bd1[idx];
        s.we1a[idx] = We1[idx];
        s.we1b[idx] = We1[HID + idx];
        s.wd2[idx]  = Wd2[idx];
    }
    for (int idx = tid; idx < LAT; idx += blockDim.x) {
        s.bo2[idx] = bo2[idx];
        s.be2[idx] = be2[idx];
    }
    for (int idx = tid; idx < Tn - 1 && idx < 128; idx += blockDim.x)
        s.dt[idx] = t[idx + 1] - t[idx];
    if (tid == 0) s.bd2 = bd2[0];
    __syncthreads();

    int warp = tid >> 5, lane = tid & 31;
    int half = lane >> 4;              // which 25 hidden units this lane owns
    int i0   = half * (HID / 2);
    int wb   = (blockIdx.x * 2 + warp) * 32;   // 32 elements per warp
    int eA = wb + (lane & 15);
    int eB = eA + 16;
    bool vA = (eA < Bn), vB = (eB < Bn);
    int cA = vA ? eA : (Bn - 1);
    int cB = vB ? eB : (Bn - 1);

    // ---------- Encoder (one-time): full 50-unit loop, both elements ----
    float2 xA = ((const float2*)x0)[cA];
    float2 xB = ((const float2*)x0)[cB];
    u64 zA[8], zB[8];
    {
        const u64* be2p = (const u64*)s.be2;
#pragma unroll
        for (int j = 0; j < 8; j++) { zA[j] = be2p[j]; zB[j] = be2p[j]; }
#pragma unroll 5
        for (int i = 0; i < HID; i++) {
            float w1a = s.we1a[i], w1b = s.we1b[i], b1 = s.be1[i];
            float hA = fmaxf(fmaf(xA.y, w1b, fmaf(xA.x, w1a, b1)), 0.0f);
            float hB = fmaxf(fmaf(xB.y, w1b, fmaf(xB.x, w1a, b1)), 0.0f);
            u64 hA2 = pk2(hA, hA), hB2 = pk2(hB, hB);
            const ulonglong2* w = (const ulonglong2*)(s.we2 + i * LAT);
#pragma unroll
            for (int j = 0; j < 4; j++) {
                ulonglong2 ww = w[j];
                zA[2 * j]     = ffma2(hA2, ww.x, zA[2 * j]);
                zA[2 * j + 1] = ffma2(hA2, ww.y, zA[2 * j + 1]);
                zB[2 * j]     = ffma2(hB2, ww.x, zB[2 * j]);
                zB[2 * j + 1] = ffma2(hB2, ww.y, zB[2 * j + 1]);
            }
        }
    }

    {
        float2 y = decode2(zA, zB, s, i0, half);
        if (half == 0) {
            if (vA) out[eA] = y.x;
            if (vB) out[eB] = y.y;
        }
    }

    // ---------- RK4 time stepping (stages fully unrolled) ----------
    for (int st = 0; st < Tn - 1; ++st) {
        float dt = s.dt[st];
        float h6 = dt * (1.0f / 6.0f);
        float h3 = dt * (1.0f / 3.0f);
        float hf = dt * 0.5f;
        u64 c6 = pk2(h6, h6), c3 = pk2(h3, h3), c2 = pk2(hf, hf), c1 = pk2(dt, dt);

        u64 znA[8], ztA[8], kkA[8];
        u64 znB[8], ztB[8], kkB[8];

        // stage 1
        ode_f2(zA, zB, kkA, kkB, s, i0, half);
#pragma unroll
        for (int j = 0; j < 8; j++) {
            znA[j] = ffma2(c6, kkA[j], zA[j]);
            ztA[j] = ffma2(c2, kkA[j], zA[j]);
            znB[j] = ffma2(c6, kkB[j], zB[j]);
            ztB[j] = ffma2(c2, kkB[j], zB[j]);
        }
        // stage 2
        ode_f2(ztA, ztB, kkA, kkB, s, i0, half);
#pragma unroll
        for (int j = 0; j < 8; j++) {
            znA[j] = ffma2(c3, kkA[j], znA[j]);
            ztA[j] = ffma2(c2, kkA[j], zA[j]);
            znB[j] = ffma2(c3, kkB[j], znB[j]);
            ztB[j] = ffma2(c2, kkB[j], zB[j]);
        }
        // stage 3
        ode_f2(ztA, ztB, kkA, kkB, s, i0, half);
#pragma unroll
        for (int j = 0; j < 8; j++) {
            znA[j] = ffma2(c3, kkA[j], znA[j]);
            ztA[j] = ffma2(c1, kkA[j], zA[j]);
            znB[j] = ffma2(c3, kkB[j], znB[j]);
            ztB[j] = ffma2(c1, kkB[j], zB[j]);
        }
        // stage 4
        ode_f2(ztA, ztB, kkA, kkB, s, i0, half);
#pragma unroll
        for (int j = 0; j < 8; j++) {
            zA[j] = ffma2(c6, kkA[j], znA[j]);
            zB[j] = ffma2(c6, kkB[j], znB[j]);
        }

        float2 y = decode2(zA, zB, s, i0, half);
        if (half == 0) {
            size_t base = (size_t)(st + 1) * Bn;
            if (vA) out[base + eA] = y.x;
            if (vB) out[base + eB] = y.y;
        }
    }
}

extern "C" void kernel_launch(void* const* d_in, const int* in_sizes, int n_in,
                              void* d_out, int out_size) {
    const float* x0  = (const float*)d_in[0];
    const float* t   = (const float*)d_in[1];
    const float* We1 = (const float*)d_in[2];
    const float* be1 = (const float*)d_in[3];
    const float* We2 = (const float*)d_in[4];
    const float* be2 = (const float*)d_in[5];
    const float* Wo1 = (const float*)d_in[6];
    const float* bo1 = (const float*)d_in[7];
    const float* Wo2 = (const float*)d_in[8];
    const float* bo2 = (const float*)d_in[9];
    const float* Wd1 = (const float*)d_in[10];
    const float* bd1 = (const float*)d_in[11];
    const float* Wd2 = (const float*)d_in[12];
    const float* bd2 = (const float*)d_in[13];

    int Bn = in_sizes[0] / 2;   // x0 is (B, 2)
    int Tn = in_sizes[1];       // t is (T,)

    int threads = 64;                 // 2 warps; 32 elements per warp
    int blocks = (Bn + 63) / 64;      // 64 elements per block
    node_kernel<<<blocks, threads>>>(x0, t, We1, be1, We2, be2, Wo1, bo1,
                                     Wo2, bo2, Wd1, bd1, Wd2, bd2,
                                     (float*)d_out, Bn, Tn);
}